// round 2
// baseline (speedup 1.0000x reference)
#include <cuda_runtime.h>
#include <cstdint>

// Hamming1Layer: y[b,c,l] = (w_self*x[b,c,l] + sum_k w_bits[k]*x[b,c,l^(1<<k)]) / 15
//                out[b,o,l] = sum_c mix_w[o,c]*y[b,c,l] + mix_b[o]
// B=32, C_IN=32, C_OUT=64, L=16384, N_BITS=14.
//
// Strategy: fuse everything. Pack adjacent l into f32x2 pairs (bit-0 neighbor is a
// register swap). 512-l tile in SMEM covers bits 0..8; bits 9..13 gather from
// global (hits L2: per-batch slice is only 2 MiB). 1/15 folded into mix_w.

#define NBITS   14
#define LPOW    16384
#define CIN     32
#define COUT    64
#define TILE_L  512
#define TPB     256
#define PAIRS   (TILE_L / 2)   // 256 pairs, one per thread

__device__ __forceinline__ uint64_t pack2(float lo, float hi) {
    uint64_t r;
    asm("mov.b64 %0, {%1, %2};" : "=l"(r) : "f"(lo), "f"(hi));
    return r;
}
__device__ __forceinline__ void unpack2(uint64_t v, float& lo, float& hi) {
    asm("mov.b64 {%0, %1}, %2;" : "=f"(lo), "=f"(hi) : "l"(v));
}
__device__ __forceinline__ uint64_t fma2(uint64_t a, uint64_t b, uint64_t c) {
    uint64_t d;
    asm("fma.rn.f32x2 %0, %1, %2, %3;" : "=l"(d) : "l"(a), "l"(b), "l"(c));
    return d;
}
__device__ __forceinline__ uint64_t mul2(uint64_t a, uint64_t b) {
    uint64_t d;
    asm("mul.rn.f32x2 %0, %1, %2;" : "=l"(d) : "l"(a), "l"(b));
    return d;
}

extern __shared__ unsigned char smem_raw[];

__global__ __launch_bounds__(TPB, 2)
void hamming_kernel(const float* __restrict__ x,
                    const float* __restrict__ w_self,
                    const float* __restrict__ w_bits,
                    const float* __restrict__ mix_w,
                    const float* __restrict__ mix_b,
                    float* __restrict__ out)
{
    // SMEM layout:
    //   sh_tile : [CIN][PAIRS] uint64 pairs of x-tile      = 64 KiB
    //   sh_w    : [CIN][COUT]  packed (w,w) mix_w/15       = 16 KiB
    //   sh_b    : [COUT]       packed (b,b) mix_b          = 512 B
    uint64_t* sh_tile = (uint64_t*)smem_raw;
    uint64_t* sh_w    = (uint64_t*)(smem_raw + (size_t)CIN * PAIRS * 8);
    uint64_t* sh_b    = sh_w + CIN * COUT;

    const int tid   = threadIdx.x;
    const int tile  = blockIdx.x;           // 0..31 (fast dim -> same-b blocks co-resident)
    const int b     = blockIdx.y;           // 0..31
    const int lbase = tile * TILE_L;

    // ---- stage weights into SMEM (1/15 folded into mix_w) ----
    const float inv15 = 1.0f / 15.0f;
    for (int e = tid; e < CIN * COUT; e += TPB) {
        int c = e / COUT, o = e % COUT;
        float v = mix_w[o * CIN + c] * inv15;
        sh_w[e] = pack2(v, v);   // sh_w[c*COUT + o]
    }
    if (tid < COUT) {
        float v = mix_b[tid];
        sh_b[tid] = pack2(v, v);
    }

    // ---- stage x tile: x[b, 0:32, lbase:lbase+512] -> SMEM (float4 coalesced) ----
    const float4* xg4   = (const float4*)(x + (size_t)b * CIN * LPOW);
    float4*       sh_t4 = (float4*)sh_tile;     // view [CIN][TILE_L/4 = 128]
    #pragma unroll
    for (int i = 0; i < (CIN * TILE_L / 4) / TPB; ++i) {   // 16 iters
        int j  = i * TPB + tid;     // 0..4095 float4 slots
        int c  = j >> 7;            // /128
        int lw = j & 127;
        sh_t4[j] = xg4[(size_t)c * (LPOW / 4) + (lbase >> 2) + lw];
    }
    __syncthreads();

    // ---- per-thread weight registers (packed pairs) ----
    const float ws = *w_self;
    const uint64_t ws2 = pack2(ws, ws);
    uint64_t wb2[NBITS];
    #pragma unroll
    for (int k = 0; k < NBITS; ++k) {
        float v = w_bits[k];        // uniform broadcast load, L1-resident
        wb2[k] = pack2(v, v);
    }

    const int p  = tid;                 // pair index in tile
    const int lg = lbase + 2 * p;       // global even l of this pair

    // ---- gather stage: y[c] = w_self*x + sum_k w_bits[k]*x[l^2^k]  (unscaled) ----
    uint64_t y[CIN];
    const uint64_t* xp = (const uint64_t*)(x + (size_t)b * CIN * LPOW);
    #pragma unroll
    for (int c = 0; c < CIN; ++c) {
        const uint64_t* row = sh_tile + c * PAIRS;
        uint64_t s = row[p];
        float slo, shi;
        unpack2(s, slo, shi);
        uint64_t acc = mul2(ws2, s);
        acc = fma2(wb2[0], pack2(shi, slo), acc);        // bit 0: swap within pair
        #pragma unroll
        for (int k = 1; k <= 8; ++k)                     // bits 1..8: inside SMEM tile
            acc = fma2(wb2[k], row[p ^ (1 << (k - 1))], acc);
        const uint64_t* grow = xp + (size_t)c * (LPOW / 2);
        #pragma unroll
        for (int k = 9; k < NBITS; ++k)                  // bits 9..13: global (L2-hot)
            acc = fma2(wb2[k], grow[(lg >> 1) ^ (1 << (k - 1))], acc);
        y[c] = acc;
    }

    // ---- mix stage: out[o] = sum_c (mix_w[o,c]/15) * y[c] + mix_b[o] ----
    uint64_t* outp = (uint64_t*)out + (size_t)b * COUT * (LPOW / 2) + (lg >> 1);
    #pragma unroll 4
    for (int o = 0; o < COUT; ++o) {
        uint64_t acc = sh_b[o];
        #pragma unroll
        for (int c = 0; c < CIN; ++c)
            acc = fma2(sh_w[c * COUT + o], y[c], acc);
        outp[(size_t)o * (LPOW / 2)] = acc;
    }
}

extern "C" void kernel_launch(void* const* d_in, const int* in_sizes, int n_in,
                              void* d_out, int out_size)
{
    const float* x      = (const float*)d_in[0];
    const float* w_self = (const float*)d_in[1];
    const float* w_bits = (const float*)d_in[2];
    const float* mix_w  = (const float*)d_in[3];
    const float* mix_b  = (const float*)d_in[4];
    float* out = (float*)d_out;

    const size_t smem_bytes = (size_t)CIN * PAIRS * 8   // tile  64 KiB
                            + (size_t)CIN * COUT * 8    // mix_w 16 KiB
                            + (size_t)COUT * 8;         // bias  512 B

    // >48 KiB dynamic SMEM opt-in. Host attribute set, not a stream op:
    // safe under graph capture; idempotent across calls.
    cudaFuncSetAttribute(hamming_kernel,
                         cudaFuncAttributeMaxDynamicSharedMemorySize,
                         (int)smem_bytes);

    dim3 grid(LPOW / TILE_L, 32, 1);   // (32 tiles, 32 batches)
    hamming_kernel<<<grid, TPB, smem_bytes>>>(x, w_self, w_bits, mix_w, mix_b, out);
}

// round 4
// speedup vs baseline: 2.3536x; 2.3536x over previous
#include <cuda_runtime.h>
#include <cstdint>

// Hamming1Layer fused kernel, v2.
// y[b,c,l] = (w_self*x[b,c,l] + sum_k w_bits[k]*x[b,c,l^(1<<k)]) / 15
// out[b,o,l] = sum_c mix_w[o,c]*y[b,c,l] + mix_b[o]
// B=32, C_IN=32, C_OUT=64, L=16384, N_BITS=14.
//
// v2 changes vs v1 (266us, L1=80.7% => spill + LDS-bound):
//  - y goes to SMEM, not a 64-reg array  -> no local-memory spills
//  - mix stage is a register-blocked GEMM: 8o x 4pair tile per thread
//    (32 packed f32x2 accumulators), 12 LDS per 32 fma2 instead of 1:1
//  - TILE_L=256: SMEM 80.5 KiB, 2 blocks/SM (16 warps)

#define NBITS   14
#define LPOW    16384
#define CIN     32
#define COUT    64
#define TILE_L  256
#define PAIRS   (TILE_L / 2)   // 128 pairs per tile
#define TPB     256

__device__ __forceinline__ uint64_t pack2(float lo, float hi) {
    uint64_t r;
    asm("mov.b64 %0, {%1, %2};" : "=l"(r) : "f"(lo), "f"(hi));
    return r;
}
__device__ __forceinline__ void unpack2(uint64_t v, float& lo, float& hi) {
    asm("mov.b64 {%0, %1}, %2;" : "=f"(lo), "=f"(hi) : "l"(v));
}
__device__ __forceinline__ uint64_t fma2(uint64_t a, uint64_t b, uint64_t c) {
    uint64_t d;
    asm("fma.rn.f32x2 %0, %1, %2, %3;" : "=l"(d) : "l"(a), "l"(b), "l"(c));
    return d;
}
__device__ __forceinline__ uint64_t mul2(uint64_t a, uint64_t b) {
    uint64_t d;
    asm("mul.rn.f32x2 %0, %1, %2;" : "=l"(d) : "l"(a), "l"(b));
    return d;
}

extern __shared__ unsigned char smem_raw[];

__global__ __launch_bounds__(TPB, 2)
void hamming_kernel(const float* __restrict__ x,
                    const float* __restrict__ w_self,
                    const float* __restrict__ w_bits,
                    const float* __restrict__ mix_w,
                    const float* __restrict__ mix_b,
                    float* __restrict__ out)
{
    // SMEM layout (u64 granularity):
    //   sh_x : [CIN][PAIRS]   x tile            32 KiB
    //   sh_y : [CIN][PAIRS]   y tile            32 KiB
    //   sh_w : [CIN][COUT]    packed mix_w/15   16 KiB
    //   sh_b : [COUT]         packed mix_b      512 B
    uint64_t* sh_x = (uint64_t*)smem_raw;
    uint64_t* sh_y = sh_x + CIN * PAIRS;
    uint64_t* sh_w = sh_y + CIN * PAIRS;
    uint64_t* sh_b = sh_w + CIN * COUT;

    const int tid   = threadIdx.x;
    const int tile  = blockIdx.x;           // 0..63
    const int b     = blockIdx.y;           // 0..31
    const int lbase = tile * TILE_L;
    const int pb    = lbase >> 1;           // global pair base (multiple of 128)

    // ---- stage weights (1/15 folded into mix_w) ----
    const float inv15 = 1.0f / 15.0f;
    for (int e = tid; e < CIN * COUT; e += TPB) {
        int c = e / COUT, o = e % COUT;
        float v = mix_w[o * CIN + c] * inv15;
        sh_w[e] = pack2(v, v);              // sh_w[c*COUT + o]
    }
    if (tid < COUT) {
        float v = mix_b[tid];
        sh_b[tid] = pack2(v, v);
    }

    // ---- stage x tile: x[b, :, lbase:lbase+256] (float4 coalesced) ----
    const float4* xg4  = (const float4*)(x + (size_t)b * CIN * LPOW);
    float4*       shx4 = (float4*)sh_x;     // [CIN][TILE_L/4 = 64]
    #pragma unroll
    for (int i = 0; i < (CIN * TILE_L / 4) / TPB; ++i) {   // 8 iters
        int j  = i * TPB + tid;             // float4 slot 0..2047
        int c  = j >> 6;
        int lw = j & 63;
        shx4[j] = xg4[(size_t)c * (LPOW / 4) + (lbase >> 2) + lw];
    }

    // per-thread packed weights
    const float ws = *w_self;
    const uint64_t ws2 = pack2(ws, ws);
    uint64_t wb2[NBITS];
    #pragma unroll
    for (int k = 0; k < NBITS; ++k) {
        float v = w_bits[k];
        wb2[k] = pack2(v, v);
    }
    __syncthreads();

    // ================= gather stage: compute y into SMEM =================
    // 32c x 128p items / 256 threads = 16 per thread. Lanes cover
    // consecutive p -> conflict-free LDS/STS, coalesced LDG.
    const uint64_t* xp = (const uint64_t*)(x + (size_t)b * CIN * LPOW);
    #pragma unroll
    for (int it = 0; it < (CIN * PAIRS) / TPB; ++it) {     // 16 iters
        int idx = it * TPB + tid;
        int c   = idx >> 7;                 // /128
        int p   = idx & 127;
        const uint64_t* row = sh_x + c * PAIRS;

        uint64_t s = row[p];
        float slo, shi;
        unpack2(s, slo, shi);
        uint64_t acc = mul2(ws2, s);
        acc = fma2(wb2[0], pack2(shi, slo), acc);          // bit 0: swap in pair
        #pragma unroll
        for (int k = 1; k <= 7; ++k)                       // bits 1..7: in tile
            acc = fma2(wb2[k], row[p ^ (1 << (k - 1))], acc);
        const uint64_t* grow = xp + (size_t)c * (LPOW / 2);
        int gp = pb + p;
        #pragma unroll
        for (int k = 8; k < NBITS; ++k)                    // bits 8..13: L2-hot global
            acc = fma2(wb2[k], grow[gp ^ (1 << (k - 1))], acc);
        sh_y[c * PAIRS + p] = acc;
    }
    __syncthreads();

    // ================= mix stage: 8o x 4pair register tile ==============
    // thread -> (ot, pt): ot = tid/32 (8 o-tiles of 8), pt = tid%32.
    // pairs: p_j = pt + 32*j, j=0..3  (lane-consecutive -> no conflicts)
    const int pt = tid & 31;
    const int ot = tid >> 5;          // 0..7
    const int ob = ot * 8;

    uint64_t acc[8][4];
    #pragma unroll
    for (int i = 0; i < 8; ++i) {
        uint64_t bias = sh_b[ob + i];
        #pragma unroll
        for (int j = 0; j < 4; ++j) acc[i][j] = bias;
    }

    #pragma unroll 8
    for (int c = 0; c < CIN; ++c) {
        uint64_t w8[8];
        #pragma unroll
        for (int i = 0; i < 8; ++i) w8[i] = sh_w[c * COUT + ob + i];   // broadcast
        uint64_t y4[4];
        #pragma unroll
        for (int j = 0; j < 4; ++j) y4[j] = sh_y[c * PAIRS + pt + 32 * j];
        #pragma unroll
        for (int i = 0; i < 8; ++i)
            #pragma unroll
            for (int j = 0; j < 4; ++j)
                acc[i][j] = fma2(w8[i], y4[j], acc[i][j]);
    }

    // ---- store: out[b, o, lbase + 2p .. ] ----
    uint64_t* outp = (uint64_t*)out + (size_t)b * COUT * (LPOW / 2) + pb;
    #pragma unroll
    for (int i = 0; i < 8; ++i) {
        uint64_t* orow = outp + (size_t)(ob + i) * (LPOW / 2);
        #pragma unroll
        for (int j = 0; j < 4; ++j)
            orow[pt + 32 * j] = acc[i][j];
    }
}

extern "C" void kernel_launch(void* const* d_in, const int* in_sizes, int n_in,
                              void* d_out, int out_size)
{
    const float* x      = (const float*)d_in[0];
    const float* w_self = (const float*)d_in[1];
    const float* w_bits = (const float*)d_in[2];
    const float* mix_w  = (const float*)d_in[3];
    const float* mix_b  = (const float*)d_in[4];
    float* out = (float*)d_out;

    const size_t smem_bytes = (size_t)CIN * PAIRS * 8 * 2   // x + y tiles  64 KiB
                            + (size_t)CIN * COUT * 8        // mix_w        16 KiB
                            + (size_t)COUT * 8;             // bias         512 B

    cudaFuncSetAttribute(hamming_kernel,
                         cudaFuncAttributeMaxDynamicSharedMemorySize,
                         (int)smem_bytes);

    dim3 grid(LPOW / TILE_L, 32, 1);   // (64 tiles, 32 batches)
    hamming_kernel<<<grid, TPB, smem_bytes>>>(x, w_self, w_bits, mix_w, mix_b, out);
}